// round 2
// baseline (speedup 1.0000x reference)
#include <cuda_runtime.h>

#define NQ   12
#define DIM  4096
#define NL   5
#define NT   256
#define KPT  8     // pairs per thread  (DIM/2/NT)
#define APT  16    // amps  per thread  (DIM/NT)

__device__ __forceinline__ float2 cmul(float2 a, float2 b) {
    return make_float2(a.x * b.x - a.y * b.y, a.x * b.y + a.y * b.x);
}

// general 2x2 complex gate applied to an amplitude pair (in-place)
__device__ __forceinline__ void apply2(const float2 u00, const float2 u01,
                                       const float2 u10, const float2 u11,
                                       float2& s0, float2& s1) {
    float2 n0, n1;
    n0.x = u00.x * s0.x - u00.y * s0.y + u01.x * s1.x - u01.y * s1.y;
    n0.y = u00.x * s0.y + u00.y * s0.x + u01.x * s1.y + u01.y * s1.x;
    n1.x = u10.x * s0.x - u10.y * s0.y + u11.x * s1.x - u11.y * s1.y;
    n1.y = u10.x * s0.y + u10.y * s0.x + u11.x * s1.y + u11.y * s1.x;
    s0 = n0; s1 = n1;
}

// low-bit gate (p in {0,1,2} -> D = 1<<p in {1,2,4}) via contiguous groups of 8
// amplitudes per thread, loaded/stored as float4 to avoid 8/4-way bank conflicts.
template <int D>
__device__ __forceinline__ void small_gate(float2* st, int tid,
                                           float2 u00, float2 u01,
                                           float2 u10, float2 u11) {
    float4* st4 = reinterpret_cast<float4*>(st);
    #pragma unroll
    for (int gg = 0; gg < DIM / 8 / NT; gg++) {      // 2 groups per thread
        int gbase = (tid + gg * NT) * 4;             // float4 index
        float4 v[4];
        #pragma unroll
        for (int q = 0; q < 4; q++) v[q] = st4[gbase + q];
        float2 a[8];
        #pragma unroll
        for (int q = 0; q < 4; q++) {
            a[2 * q]     = make_float2(v[q].x, v[q].y);
            a[2 * q + 1] = make_float2(v[q].z, v[q].w);
        }
        #pragma unroll
        for (int m = 0; m < 8; m++) {
            if ((m & D) == 0) apply2(u00, u01, u10, u11, a[m], a[m + D]);
        }
        #pragma unroll
        for (int q = 0; q < 4; q++)
            st4[gbase + q] = make_float4(a[2 * q].x, a[2 * q].y,
                                         a[2 * q + 1].x, a[2 * q + 1].y);
    }
}

__global__ void __launch_bounds__(NT)
qnet_kernel(const float* __restrict__ x,
            const float* __restrict__ iw,
            const float* __restrict__ th,
            const float* __restrict__ ow,
            float* __restrict__ out) {
    __shared__ __align__(16) float2 st[DIM];   // 32 KB state vector
    __shared__ float2 Ush[NQ][4];              // per-layer fused 2x2 gates
    __shared__ float red0[NT / 32], red1[NT / 32];

    const int b   = blockIdx.x;
    const int tid = threadIdx.x;

    // batch-dependent input encoding (only lanes 0..11 need it)
    float xin = 0.f;
    if (tid < NQ) xin = tanhf(x[b * NQ + tid]);

    // Precompute CNOT-ring permutation sources (same for every layer/batch).
    // Ring: CNOT(c=i, t=(i+1)%NQ) for i = 0..NQ-1 applied in order.
    // For output index j: src = M_0(M_1(...M_{NQ-1}(j))), each M an involution.
    int src[APT];
    #pragma unroll
    for (int k = 0; k < APT; k++) {
        int s = tid + (k << 8);
        #pragma unroll
        for (int i = NQ - 1; i >= 0; --i) {
            int pc = NQ - 1 - i;                                  // control bit pos
            int pt = (i == NQ - 1) ? (NQ - 1) : (NQ - 2 - i);     // target bit pos
            s ^= ((s >> pc) & 1) << pt;
        }
        src[k] = s;
    }

    #pragma unroll 1
    for (int l = 0; l < NL; l++) {
        // ---- build fused U_j = RZ(b)*RY(a)*RX(g) for each qubit (lanes 0..11) ----
        if (tid < NQ) {
            float g  = 0.5f * iw[l * NQ + tid] * xin;
            float aa = 0.5f * th[(l * NQ + tid) * 2 + 0];
            float bb = 0.5f * th[(l * NQ + tid) * 2 + 1];
            float sg, cg, sa, ca, sb, cb;
            __sincosf(g,  &sg, &cg);
            __sincosf(aa, &sa, &ca);
            __sincosf(bb, &sb, &cb);
            float cc = ca * cg, ss = sa * sg, sc = sa * cg, cs = ca * sg;
            // M = RY*RX:
            //   M00 = cc + i ss,  M01 = -sc - i cs
            //   M10 = sc - i cs,  M11 =  cc - i ss
            float2 e0 = make_float2(cb, -sb);   // row 0 scaled by e^{-ib}
            float2 e1 = make_float2(cb,  sb);   // row 1 scaled by e^{+ib}
            Ush[tid][0] = cmul(e0, make_float2(cc,  ss));
            Ush[tid][1] = cmul(e0, make_float2(-sc, -cs));
            Ush[tid][2] = cmul(e1, make_float2(sc,  -cs));
            Ush[tid][3] = cmul(e1, make_float2(cc,  -ss));
        }
        __syncthreads();

        if (l == 0) {
            // |0..0> -> product state after 12 single-qubit gates:
            // amp(j) = prod_q (bit_q(j)==0 ? U_q00 : U_q10), bit_q at position NQ-1-q
            float2 plow = make_float2(1.f, 0.f);
            #pragma unroll
            for (int q = 4; q < NQ; q++) {
                int bit = (tid >> (NQ - 1 - q)) & 1;
                plow = cmul(plow, Ush[q][bit ? 2 : 0]);
            }
            #pragma unroll
            for (int k = 0; k < APT; k++) {
                float2 amp = plow;
                #pragma unroll
                for (int q = 0; q < 4; q++) {
                    int bit = (k >> (3 - q)) & 1;
                    amp = cmul(amp, Ush[q][bit ? 2 : 0]);
                }
                st[tid + (k << 8)] = amp;
            }
            __syncthreads();
        } else {
            // gates on high bit positions p = 11..3 (qubits j = 0..8)
            #pragma unroll 1
            for (int j = 0; j < 9; j++) {
                const int p = NQ - 1 - j;
                const float2 u00 = Ush[j][0], u01 = Ush[j][1];
                const float2 u10 = Ush[j][2], u11 = Ush[j][3];
                const int mask = (1 << p) - 1;
                const int hp   = 1 << p;
                #pragma unroll
                for (int kk = 0; kk < KPT; kk++) {
                    int k  = tid + (kk << 8);
                    int i0 = ((k & ~mask) << 1) | (k & mask);
                    int i1 = i0 | hp;
                    float2 s0 = st[i0], s1 = st[i1];
                    apply2(u00, u01, u10, u11, s0, s1);
                    st[i0] = s0; st[i1] = s1;
                }
                __syncthreads();
            }
            // low bit positions p = 2,1,0 (qubits 9,10,11) via float4 groups
            small_gate<4>(st, tid, Ush[9][0],  Ush[9][1],  Ush[9][2],  Ush[9][3]);
            __syncthreads();
            small_gate<2>(st, tid, Ush[10][0], Ush[10][1], Ush[10][2], Ush[10][3]);
            __syncthreads();
            small_gate<1>(st, tid, Ush[11][0], Ush[11][1], Ush[11][2], Ush[11][3]);
            __syncthreads();
        }

        // ---- fused CNOT ring as one permutation pass ----
        {
            float2 tmp[APT];
            #pragma unroll
            for (int k = 0; k < APT; k++) tmp[k] = st[src[k]];
            __syncthreads();
            #pragma unroll
            for (int k = 0; k < APT; k++) st[tid + (k << 8)] = tmp[k];
            __syncthreads();
        }
    }

    // ---- measurement: e01 uses bits 11^10, e23 uses bits 9^8 ----
    float e01 = 0.f, e23 = 0.f;
    #pragma unroll
    for (int k = 0; k < APT; k++) {
        int   jdx = tid + (k << 8);
        float2 v  = st[jdx];
        float pr  = v.x * v.x + v.y * v.y;
        e01 += (((jdx >> 11) ^ (jdx >> 10)) & 1) ? -pr : pr;
        e23 += (((jdx >> 9)  ^ (jdx >> 8))  & 1) ? -pr : pr;
    }
    #pragma unroll
    for (int off = 16; off > 0; off >>= 1) {
        e01 += __shfl_down_sync(0xffffffffu, e01, off);
        e23 += __shfl_down_sync(0xffffffffu, e23, off);
    }
    if ((tid & 31) == 0) { red0[tid >> 5] = e01; red1[tid >> 5] = e23; }
    __syncthreads();
    if (tid == 0) {
        float s1 = 0.f, s2 = 0.f;
        #pragma unroll
        for (int w = 0; w < NT / 32; w++) { s1 += red0[w]; s2 += red1[w]; }
        out[b * 2 + 0] = ow[0] * s1;
        out[b * 2 + 1] = ow[1] * s2;
    }
}

extern "C" void kernel_launch(void* const* d_in, const int* in_sizes, int n_in,
                              void* d_out, int out_size) {
    const float* x  = (const float*)d_in[0];   // (BATCH, 12)
    const float* iw = (const float*)d_in[1];   // (5, 12)
    const float* th = (const float*)d_in[2];   // (5, 12, 2)
    const float* ow = (const float*)d_in[3];   // (2,)
    float* out = (float*)d_out;                // (BATCH, 2)
    int batch = in_sizes[0] / NQ;
    qnet_kernel<<<batch, NT>>>(x, iw, th, ow, out);
}

// round 3
// speedup vs baseline: 2.3853x; 2.3853x over previous
#include <cuda_runtime.h>

#define NQ   12
#define DIM  4096
#define NL   5
#define NT   256
#define PAD_DIM (DIM + DIM / 16)   // stride-17 padded state: 4352 float2 = 34 KB

__device__ __forceinline__ float2 cmul(float2 a, float2 b) {
    return make_float2(a.x * b.x - a.y * b.y, a.x * b.y + a.y * b.x);
}

// general 2x2 complex gate on an amplitude pair (in-place)
__device__ __forceinline__ void apply2(const float2 u00, const float2 u01,
                                       const float2 u10, const float2 u11,
                                       float2& s0, float2& s1) {
    float2 n0, n1;
    n0.x = u00.x * s0.x - u00.y * s0.y + u01.x * s1.x - u01.y * s1.y;
    n0.y = u00.x * s0.y + u00.y * s0.x + u01.x * s1.y + u01.y * s1.x;
    n1.x = u10.x * s0.x - u10.y * s0.y + u11.x * s1.x - u11.y * s1.y;
    n1.y = u10.x * s0.y + u10.y * s0.x + u11.x * s1.y + u11.y * s1.x;
    s0 = n0; s1 = n1;
}

// apply 4 gates: register-nibble bit m (pair stride 1<<m) <-> qubit QBASE - m
template <int QBASE>
__device__ __forceinline__ void gates4(float2 a[16], const float4* U) {
    #pragma unroll
    for (int m = 0; m < 4; m++) {
        const int q = QBASE - m;
        float4 r0 = U[q * 2 + 0];
        float4 r1 = U[q * 2 + 1];
        float2 u00 = make_float2(r0.x, r0.y), u01 = make_float2(r0.z, r0.w);
        float2 u10 = make_float2(r1.x, r1.y), u11 = make_float2(r1.z, r1.w);
        #pragma unroll
        for (int k = 0; k < 16; k++)
            if (!(k & (1 << m)))
                apply2(u00, u01, u10, u11, a[k], a[k | (1 << m)]);
    }
}

// fused U_q = RZ(b) * RY(a) * RX(g), written as two float4 rows
__device__ __forceinline__ void buildU(float4* U, int l, int tid, float xin,
                                       const float* __restrict__ iw,
                                       const float* __restrict__ th) {
    float g  = 0.5f * iw[l * NQ + tid] * xin;
    float aa = 0.5f * th[(l * NQ + tid) * 2 + 0];
    float bb = 0.5f * th[(l * NQ + tid) * 2 + 1];
    float sg, cg, sa, ca, sb, cb;
    __sincosf(g,  &sg, &cg);
    __sincosf(aa, &sa, &ca);
    __sincosf(bb, &sb, &cb);
    float cc = ca * cg, ss = sa * sg, sc = sa * cg, cs = ca * sg;
    float2 e0 = make_float2(cb, -sb);
    float2 e1 = make_float2(cb,  sb);
    float2 u00 = cmul(e0, make_float2(cc,   ss));
    float2 u01 = cmul(e0, make_float2(-sc, -cs));
    float2 u10 = cmul(e1, make_float2(sc,  -cs));
    float2 u11 = cmul(e1, make_float2(cc,  -ss));
    U[tid * 2 + 0] = make_float4(u00.x, u00.y, u01.x, u01.y);
    U[tid * 2 + 1] = make_float4(u10.x, u10.y, u11.x, u11.y);
}

__global__ void __launch_bounds__(NT)
qnet_kernel(const float* __restrict__ x,
            const float* __restrict__ iw,
            const float* __restrict__ th,
            const float* __restrict__ ow,
            float* __restrict__ out) {
    __shared__ __align__(16) float2 st[PAD_DIM];
    __shared__ float4 Ush4[NQ * 2];
    __shared__ float red0[NT / 32], red1[NT / 32];

    const int b   = blockIdx.x;
    const int tid = threadIdx.x;

    float xin = 0.f;
    if (tid < NQ) xin = tanhf(x[b * NQ + tid]);

    // CNOT-ring permutation, closed form (GF(2)-linear):
    // src(tid*16 + k) = src_t ^ SRCK[k]
    const int src_t = ((tid & 1) << 3) | ((tid ^ (tid >> 1)) << 4);
    const int SRCK[16] = {0x000, 0xC01, 0x003, 0xC02, 0x006, 0xC07, 0x005, 0xC04,
                          0x00C, 0xC0D, 0x00F, 0xC0E, 0x00A, 0xC0B, 0x009, 0xC08};

    // per-phase base indices in the padded (stride-17) layout: loc = j + (j>>4)
    const int bA = 17 * tid;                              // phase A: element k at bA + k
    const int bB = 17 * (tid & 0xF0) + (tid & 15);        // phase B: element k at bB + 17k
    const int bC = tid + (tid >> 4);                      // phase C: element k at bC + 272k

    float2 a[16];

    // ---------------- layer 0: product state directly in phase-C layout --------
    if (tid < NQ) buildU(Ush4, 0, tid, xin, iw, th);
    __syncthreads();
    {
        // j = (k << 8) | tid ; qubit q <-> index bit 11-q
        float2 plow = make_float2(1.f, 0.f);
        #pragma unroll
        for (int p = 0; p < 8; p++) {
            int q = 11 - p;
            float4 row = ((tid >> p) & 1) ? Ush4[q * 2 + 1] : Ush4[q * 2 + 0];
            plow = cmul(plow, make_float2(row.x, row.y));
        }
        #pragma unroll
        for (int k = 0; k < 16; k++) {
            float2 amp = plow;
            #pragma unroll
            for (int m = 0; m < 4; m++) {
                int q = 3 - m;
                float4 row = ((k >> m) & 1) ? Ush4[q * 2 + 1] : Ush4[q * 2 + 0];
                amp = cmul(amp, make_float2(row.x, row.y));
            }
            st[bC + 272 * k] = amp;
        }
    }
    __syncthreads();

    // ---------------- layers 1..4 ---------------------------------------------
    #pragma unroll 1
    for (int l = 1; l < NL; l++) {
        if (tid < NQ) buildU(Ush4, l, tid, xin, iw, th);

        // phase A load = gather that applies the PREVIOUS layer's CNOT ring
        #pragma unroll
        for (int k = 0; k < 16; k++) {
            int s = src_t ^ SRCK[k];
            a[k] = st[s + (s >> 4)];
        }
        __syncthreads();                 // gather done before stores clobber st
        gates4<11>(a, Ush4);             // qubits 11,10,9,8  (bits 0..3)
        #pragma unroll
        for (int k = 0; k < 16; k++) st[bA + k] = a[k];
        __syncthreads();

        // phase B (load/store same addresses -> no mid-phase sync needed)
        #pragma unroll
        for (int k = 0; k < 16; k++) a[k] = st[bB + 17 * k];
        gates4<7>(a, Ush4);              // qubits 7,6,5,4    (bits 4..7)
        #pragma unroll
        for (int k = 0; k < 16; k++) st[bB + 17 * k] = a[k];
        __syncthreads();

        // phase C
        #pragma unroll
        for (int k = 0; k < 16; k++) a[k] = st[bC + 272 * k];
        gates4<3>(a, Ush4);              // qubits 3,2,1,0    (bits 8..11)
        #pragma unroll
        for (int k = 0; k < 16; k++) st[bC + 272 * k] = a[k];
        __syncthreads();
    }

    // ---------------- measurement (fuses final CNOT ring into the gather) ------
    // post-perm index j' = tid*16 + k: bit11=tid7, bit10=tid6, bit9=tid5, bit8=tid4
    float sacc = 0.f;
    #pragma unroll
    for (int k = 0; k < 16; k++) {
        int s = src_t ^ SRCK[k];
        float2 v = st[s + (s >> 4)];
        sacc += v.x * v.x + v.y * v.y;
    }
    float e01 = (((tid >> 7) ^ (tid >> 6)) & 1) ? -sacc : sacc;
    float e23 = (((tid >> 5) ^ (tid >> 4)) & 1) ? -sacc : sacc;

    #pragma unroll
    for (int off = 16; off > 0; off >>= 1) {
        e01 += __shfl_down_sync(0xffffffffu, e01, off);
        e23 += __shfl_down_sync(0xffffffffu, e23, off);
    }
    if ((tid & 31) == 0) { red0[tid >> 5] = e01; red1[tid >> 5] = e23; }
    __syncthreads();
    if (tid == 0) {
        float s1 = 0.f, s2 = 0.f;
        #pragma unroll
        for (int w = 0; w < NT / 32; w++) { s1 += red0[w]; s2 += red1[w]; }
        out[b * 2 + 0] = ow[0] * s1;
        out[b * 2 + 1] = ow[1] * s2;
    }
}

extern "C" void kernel_launch(void* const* d_in, const int* in_sizes, int n_in,
                              void* d_out, int out_size) {
    const float* x  = (const float*)d_in[0];   // (BATCH, 12)
    const float* iw = (const float*)d_in[1];   // (5, 12)
    const float* th = (const float*)d_in[2];   // (5, 12, 2)
    const float* ow = (const float*)d_in[3];   // (2,)
    float* out = (float*)d_out;                // (BATCH, 2)
    int batch = in_sizes[0] / NQ;
    qnet_kernel<<<batch, NT>>>(x, iw, th, ow, out);
}

// round 4
// speedup vs baseline: 2.6243x; 1.1002x over previous
#include <cuda_runtime.h>

#define NQ   12
#define DIM  4096
#define NL   5
#define NT   256
#define PAD_DIM (DIM + DIM / 16)   // stride-17 padded state: 4352 float2 = 34 KB

typedef unsigned long long ull;

__device__ __forceinline__ ull f32x2_mul(ull a, ull b) {
    ull r;
    asm("mul.rn.f32x2 %0, %1, %2;" : "=l"(r) : "l"(a), "l"(b));
    return r;
}
__device__ __forceinline__ ull f32x2_fma(ull a, ull b, ull c) {
    ull r;
    asm("fma.rn.f32x2 %0, %1, %2, %3;" : "=l"(r) : "l"(a), "l"(b), "l"(c));
    return r;
}
__device__ __forceinline__ ull swap_halves(ull v) {
    uint2 t = *reinterpret_cast<uint2*>(&v);
    uint2 s = make_uint2(t.y, t.x);
    return *reinterpret_cast<ull*>(&s);
}
__device__ __forceinline__ ull pack2(float lo, float hi) {
    uint2 t = make_uint2(__float_as_uint(lo), __float_as_uint(hi));
    return *reinterpret_cast<ull*>(&t);
}

__device__ __forceinline__ float2 cmul(float2 a, float2 b) {
    return make_float2(a.x * b.x - a.y * b.y, a.x * b.y + a.y * b.x);
}

// packed complex accumulate: n += u * s, with u given as (c = dup(u.x), d = (-u.y, u.y))
__device__ __forceinline__ ull cfma_p(ull c, ull d, ull s, ull sw, ull n) {
    n = f32x2_fma(c, s,  n);
    n = f32x2_fma(d, sw, n);
    return n;
}

// apply 4 gates: register-nibble bit m (pair stride 1<<m) <-> qubit QBASE - m
// U layout per qubit q: 4 x ulonglong2 = {c00,d00},{c01,d01},{c10,d10},{c11,d11}
template <int QBASE>
__device__ __forceinline__ void gates4p(ull a[16], const ulonglong2* __restrict__ U) {
    #pragma unroll
    for (int m = 0; m < 4; m++) {
        const int q = QBASE - m;
        const ulonglong2 p0 = U[q * 4 + 0];
        const ulonglong2 p1 = U[q * 4 + 1];
        const ulonglong2 p2 = U[q * 4 + 2];
        const ulonglong2 p3 = U[q * 4 + 3];
        #pragma unroll
        for (int k = 0; k < 16; k++) {
            if (!(k & (1 << m))) {
                ull s0 = a[k], s1 = a[k | (1 << m)];
                ull s0w = swap_halves(s0), s1w = swap_halves(s1);
                ull n0 = f32x2_mul(p0.x, s0);
                n0 = f32x2_fma(p0.y, s0w, n0);
                n0 = cfma_p(p1.x, p1.y, s1, s1w, n0);
                ull n1 = f32x2_mul(p2.x, s0);
                n1 = f32x2_fma(p2.y, s0w, n1);
                n1 = cfma_p(p3.x, p3.y, s1, s1w, n1);
                a[k] = n0; a[k | (1 << m)] = n1;
            }
        }
    }
}

// fused U_q = RZ(b)*RY(a)*RX(g); writes packed-dup coefficient rows and plain u00/u10
__device__ __forceinline__ void buildU(ulonglong2* Up, float2* U00, float2* U10,
                                       int l, int tid, float xin,
                                       const float* __restrict__ iw,
                                       const float* __restrict__ th) {
    float g  = 0.5f * iw[l * NQ + tid] * xin;
    float aa = 0.5f * th[(l * NQ + tid) * 2 + 0];
    float bb = 0.5f * th[(l * NQ + tid) * 2 + 1];
    float sg, cg, sa, ca, sb, cb;
    __sincosf(g,  &sg, &cg);
    __sincosf(aa, &sa, &ca);
    __sincosf(bb, &sb, &cb);
    float cc = ca * cg, ss = sa * sg, sc = sa * cg, cs = ca * sg;
    float2 e0 = make_float2(cb, -sb);
    float2 e1 = make_float2(cb,  sb);
    float2 u00 = cmul(e0, make_float2(cc,   ss));
    float2 u01 = cmul(e0, make_float2(-sc, -cs));
    float2 u10 = cmul(e1, make_float2(sc,  -cs));
    float2 u11 = cmul(e1, make_float2(cc,  -ss));
    Up[tid * 4 + 0] = make_ulonglong2(pack2(u00.x, u00.x), pack2(-u00.y, u00.y));
    Up[tid * 4 + 1] = make_ulonglong2(pack2(u01.x, u01.x), pack2(-u01.y, u01.y));
    Up[tid * 4 + 2] = make_ulonglong2(pack2(u10.x, u10.x), pack2(-u10.y, u10.y));
    Up[tid * 4 + 3] = make_ulonglong2(pack2(u11.x, u11.x), pack2(-u11.y, u11.y));
    U00[tid] = u00;
    U10[tid] = u10;
}

__global__ void __launch_bounds__(NT)
qnet_kernel(const float* __restrict__ x,
            const float* __restrict__ iw,
            const float* __restrict__ th,
            const float* __restrict__ ow,
            float* __restrict__ out) {
    __shared__ __align__(16) float2 st[PAD_DIM];
    __shared__ __align__(16) ulonglong2 Up[NQ * 4];   // packed-dup gate coeffs
    __shared__ float2 U00s[NQ], U10s[NQ];             // plain col-0 entries (layer 0 init)
    __shared__ float red0[NT / 32], red1[NT / 32];

    const int b   = blockIdx.x;
    const int tid = threadIdx.x;

    float xin = 0.f;
    if (tid < NQ) xin = tanhf(x[b * NQ + tid]);

    // CNOT-ring permutation, closed form: src(tid*16+k) = src_t ^ SRCK[k]
    const int src_t = ((tid & 1) << 3) | ((tid ^ (tid >> 1)) << 4);
    const int SRCK[16] = {0x000, 0xC01, 0x003, 0xC02, 0x006, 0xC07, 0x005, 0xC04,
                          0x00C, 0xC0D, 0x00F, 0xC0E, 0x00A, 0xC0B, 0x009, 0xC08};

    // per-phase base indices in the padded layout: loc = j + (j>>4)
    const int bA = 17 * tid;                           // phase A: k at bA + k
    const int bB = 17 * (tid & 0xF0) + (tid & 15);     // phase B: k at bB + 17k
    const int bC = tid + (tid >> 4);                   // phase C: k at bC + 272k

    ull* st64 = reinterpret_cast<ull*>(st);
    ull a[16];

    // ---------------- layer 0: product state directly in phase-C layout --------
    if (tid < NQ) buildU(Up, U00s, U10s, 0, tid, xin, iw, th);
    __syncthreads();
    {
        // j = (k << 8) | tid ; qubit q <-> index bit 11-q
        float2 plow = make_float2(1.f, 0.f);
        #pragma unroll
        for (int p = 0; p < 8; p++) {
            int q = 11 - p;
            float2 row = ((tid >> p) & 1) ? U10s[q] : U00s[q];
            plow = cmul(plow, row);
        }
        #pragma unroll
        for (int k = 0; k < 16; k++) {
            float2 amp = plow;
            #pragma unroll
            for (int m = 0; m < 4; m++) {
                int q = 3 - m;
                float2 row = ((k >> m) & 1) ? U10s[q] : U00s[q];
                amp = cmul(amp, row);
            }
            st[bC + 272 * k] = amp;
        }
    }
    __syncthreads();

    // ---------------- layers 1..4 ---------------------------------------------
    #pragma unroll 1
    for (int l = 1; l < NL; l++) {
        if (tid < NQ) buildU(Up, U00s, U10s, l, tid, xin, iw, th);

        // phase A load = gather applying the PREVIOUS layer's CNOT ring
        #pragma unroll
        for (int k = 0; k < 16; k++) {
            int s = src_t ^ SRCK[k];
            a[k] = st64[s + (s >> 4)];
        }
        __syncthreads();                 // gather (and buildU) done before stores
        gates4p<11>(a, Up);              // qubits 11,10,9,8  (bits 0..3)
        #pragma unroll
        for (int k = 0; k < 16; k++) st64[bA + k] = a[k];
        __syncthreads();

        // phase B (load/store same addresses -> no mid-phase sync needed)
        #pragma unroll
        for (int k = 0; k < 16; k++) a[k] = st64[bB + 17 * k];
        gates4p<7>(a, Up);               // qubits 7,6,5,4    (bits 4..7)
        #pragma unroll
        for (int k = 0; k < 16; k++) st64[bB + 17 * k] = a[k];
        __syncthreads();

        // phase C
        #pragma unroll
        for (int k = 0; k < 16; k++) a[k] = st64[bC + 272 * k];
        gates4p<3>(a, Up);               // qubits 3,2,1,0    (bits 8..11)
        #pragma unroll
        for (int k = 0; k < 16; k++) st64[bC + 272 * k] = a[k];
        __syncthreads();
    }

    // ---------------- measurement (fuses final CNOT ring into the gather) ------
    float sacc = 0.f;
    #pragma unroll
    for (int k = 0; k < 16; k++) {
        int s = src_t ^ SRCK[k];
        float2 v = st[s + (s >> 4)];
        sacc += v.x * v.x + v.y * v.y;
    }
    float e01 = (((tid >> 7) ^ (tid >> 6)) & 1) ? -sacc : sacc;
    float e23 = (((tid >> 5) ^ (tid >> 4)) & 1) ? -sacc : sacc;

    #pragma unroll
    for (int off = 16; off > 0; off >>= 1) {
        e01 += __shfl_down_sync(0xffffffffu, e01, off);
        e23 += __shfl_down_sync(0xffffffffu, e23, off);
    }
    if ((tid & 31) == 0) { red0[tid >> 5] = e01; red1[tid >> 5] = e23; }
    __syncthreads();
    if (tid == 0) {
        float s1 = 0.f, s2 = 0.f;
        #pragma unroll
        for (int w = 0; w < NT / 32; w++) { s1 += red0[w]; s2 += red1[w]; }
        out[b * 2 + 0] = ow[0] * s1;
        out[b * 2 + 1] = ow[1] * s2;
    }
}

extern "C" void kernel_launch(void* const* d_in, const int* in_sizes, int n_in,
                              void* d_out, int out_size) {
    const float* x  = (const float*)d_in[0];   // (BATCH, 12)
    const float* iw = (const float*)d_in[1];   // (5, 12)
    const float* th = (const float*)d_in[2];   // (5, 12, 2)
    const float* ow = (const float*)d_in[3];   // (2,)
    float* out = (float*)d_out;                // (BATCH, 2)
    int batch = in_sizes[0] / NQ;
    qnet_kernel<<<batch, NT>>>(x, iw, th, ow, out);
}

// round 5
// speedup vs baseline: 2.7549x; 1.0498x over previous
#include <cuda_runtime.h>

#define NQ   12
#define DIM  4096
#define NL   5
#define NT   256
// pad-2 layout: loc(j) = j + 2*(j>>4)  -> stride-18 rows, 16B-aligned rows
#define PAD_DIM (DIM + 2 * (DIM / 16))   // 4608 ull = 36 KB

typedef unsigned long long ull;

__device__ __forceinline__ ull f32x2_mul(ull a, ull b) {
    ull r;
    asm("mul.rn.f32x2 %0, %1, %2;" : "=l"(r) : "l"(a), "l"(b));
    return r;
}
__device__ __forceinline__ ull f32x2_fma(ull a, ull b, ull c) {
    ull r;
    asm("fma.rn.f32x2 %0, %1, %2, %3;" : "=l"(r) : "l"(a), "l"(b), "l"(c));
    return r;
}
__device__ __forceinline__ ull swap_halves(ull v) {
    uint2 t = *reinterpret_cast<uint2*>(&v);
    uint2 s = make_uint2(t.y, t.x);
    return *reinterpret_cast<ull*>(&s);
}
__device__ __forceinline__ ull pack2(float lo, float hi) {
    uint2 t = make_uint2(__float_as_uint(lo), __float_as_uint(hi));
    return *reinterpret_cast<ull*>(&t);
}
__device__ __forceinline__ float2 cmul(float2 a, float2 b) {
    return make_float2(a.x * b.x - a.y * b.y, a.x * b.y + a.y * b.x);
}

// apply 4 gates: register-nibble bit m (pair stride 1<<m) <-> qubit QBASE - m
// U layout per qubit q: 4 x ulonglong2 = {c00,d00},{c01,d01},{c10,d10},{c11,d11}
template <int QBASE>
__device__ __forceinline__ void gates4p(ull a[16], const ulonglong2* __restrict__ U) {
    #pragma unroll
    for (int m = 0; m < 4; m++) {
        const int q = QBASE - m;
        const ulonglong2 p0 = U[q * 4 + 0];
        const ulonglong2 p1 = U[q * 4 + 1];
        const ulonglong2 p2 = U[q * 4 + 2];
        const ulonglong2 p3 = U[q * 4 + 3];
        #pragma unroll
        for (int k = 0; k < 16; k++) {
            if (!(k & (1 << m))) {
                ull s0 = a[k], s1 = a[k | (1 << m)];
                ull s0w = swap_halves(s0), s1w = swap_halves(s1);
                ull n0 = f32x2_mul(p0.x, s0);
                n0 = f32x2_fma(p0.y, s0w, n0);
                n0 = f32x2_fma(p1.x, s1,  n0);
                n0 = f32x2_fma(p1.y, s1w, n0);
                ull n1 = f32x2_mul(p2.x, s0);
                n1 = f32x2_fma(p2.y, s0w, n1);
                n1 = f32x2_fma(p3.x, s1,  n1);
                n1 = f32x2_fma(p3.y, s1w, n1);
                a[k] = n0; a[k | (1 << m)] = n1;
            }
        }
    }
}

__global__ void __launch_bounds__(NT, 4)
qnet_kernel(const float* __restrict__ x,
            const float* __restrict__ iw,
            const float* __restrict__ th,
            const float* __restrict__ ow,
            float* __restrict__ out) {
    __shared__ __align__(16) ull st[PAD_DIM];          // 36 KB state (packed complex)
    __shared__ __align__(16) ulonglong2 Up[NL * NQ * 4];  // all layers' gates, 3.75 KB
    __shared__ float2 U00s[NQ], U10s[NQ];              // layer-0 col-0 entries
    __shared__ float red0[NT / 32], red1[NT / 32];

    const int b   = blockIdx.x;
    const int tid = threadIdx.x;

    // ---- build ALL layers' fused gates up front: one thread per (layer,qubit) ----
    if (tid < NL * NQ) {
        const int l = tid / NQ, q = tid % NQ;
        float xin = tanhf(x[b * NQ + q]);
        float g  = 0.5f * iw[l * NQ + q] * xin;
        float aa = 0.5f * th[(l * NQ + q) * 2 + 0];
        float bb = 0.5f * th[(l * NQ + q) * 2 + 1];
        float sg, cg, sa, ca, sb, cb;
        __sincosf(g,  &sg, &cg);
        __sincosf(aa, &sa, &ca);
        __sincosf(bb, &sb, &cb);
        float cc = ca * cg, ss = sa * sg, sc = sa * cg, cs = ca * sg;
        float2 e0 = make_float2(cb, -sb);
        float2 e1 = make_float2(cb,  sb);
        float2 u00 = cmul(e0, make_float2(cc,   ss));
        float2 u01 = cmul(e0, make_float2(-sc, -cs));
        float2 u10 = cmul(e1, make_float2(sc,  -cs));
        float2 u11 = cmul(e1, make_float2(cc,  -ss));
        ulonglong2* Uq = Up + (l * NQ + q) * 4;
        Uq[0] = make_ulonglong2(pack2(u00.x, u00.x), pack2(-u00.y, u00.y));
        Uq[1] = make_ulonglong2(pack2(u01.x, u01.x), pack2(-u01.y, u01.y));
        Uq[2] = make_ulonglong2(pack2(u10.x, u10.x), pack2(-u10.y, u10.y));
        Uq[3] = make_ulonglong2(pack2(u11.x, u11.x), pack2(-u11.y, u11.y));
        if (l == 0) { U00s[q] = u00; U10s[q] = u10; }
    }

    // ---- CNOT-ring scatter map (inverse perm), GF(2)-linear closed form ----
    // dst(j) = F(j); for tid (8 low bits): F(tid) = invgray(tid) ^ (parity<<11)
    int gt = tid ^ (tid >> 1); gt ^= gt >> 2; gt ^= gt >> 4;
    const int F_t = gt ^ ((gt & 1) << 11);
    // F(k<<8) for k = bits[11:8]
    const int DSTK[16] = {0x000, 0x9FF, 0xBFF, 0x200, 0xFFF, 0x600, 0x400, 0xDFF,
                          0x7FF, 0xE00, 0xC00, 0x5FF, 0x800, 0x1FF, 0x3FF, 0xA00};

    // phase base indices (ull units) in pad-2 layout
    const int bB = 18 * (tid & 0xF0) + (tid & 15);   // phase B: k at bB + 18k
    const int bC = tid + 2 * (tid >> 4);             // phase C: k at bC + 288k
    ulonglong2* st128 = reinterpret_cast<ulonglong2*>(st);

    ull a[16];
    __syncthreads();

    // ---------------- layer 0: product state, scatter-stored (post-perm) -------
    {
        float2 plow = make_float2(1.f, 0.f);
        #pragma unroll
        for (int p = 0; p < 8; p++) {                 // tid bit p <-> qubit 11-p
            float2 row = ((tid >> p) & 1) ? U10s[11 - p] : U00s[11 - p];
            plow = cmul(plow, row);
        }
        #pragma unroll
        for (int k = 0; k < 16; k++) {                // j = (k<<8) | tid
            float2 amp = plow;
            #pragma unroll
            for (int m = 0; m < 4; m++) {             // j bit 8+m <-> qubit 3-m
                float2 row = ((k >> m) & 1) ? U10s[3 - m] : U00s[3 - m];
                amp = cmul(amp, row);
            }
            int d = DSTK[k] ^ F_t;
            st[d + 2 * (d >> 4)] = pack2(amp.x, amp.y);
        }
    }
    __syncthreads();

    // ---------------- layers 1..4: A (contig) -> B -> C + scatter --------------
    #pragma unroll 1
    for (int l = 1; l < NL; l++) {
        const ulonglong2* Ul = Up + l * (NQ * 4);

        // phase A: thread-local contiguous, 128-bit accesses, no internal sync
        #pragma unroll
        for (int q = 0; q < 8; q++) {
            ulonglong2 v = st128[9 * tid + q];
            a[2 * q] = v.x; a[2 * q + 1] = v.y;
        }
        gates4p<11>(a, Ul);                       // qubits 11,10,9,8 (bits 0..3)
        #pragma unroll
        for (int q = 0; q < 8; q++)
            st128[9 * tid + q] = make_ulonglong2(a[2 * q], a[2 * q + 1]);
        __syncthreads();

        // phase B
        #pragma unroll
        for (int k = 0; k < 16; k++) a[k] = st[bB + 18 * k];
        gates4p<7>(a, Ul);                        // qubits 7,6,5,4 (bits 4..7)
        #pragma unroll
        for (int k = 0; k < 16; k++) st[bB + 18 * k] = a[k];
        __syncthreads();

        // phase C + CNOT-ring scatter
        #pragma unroll
        for (int k = 0; k < 16; k++) a[k] = st[bC + 288 * k];
        gates4p<3>(a, Ul);                        // qubits 3,2,1,0 (bits 8..11)
        #pragma unroll
        for (int k = 0; k < 16; k++) {
            int d = DSTK[k] ^ F_t;
            st[d + 2 * (d >> 4)] = a[k];
        }
        __syncthreads();
    }

    // ---------------- measurement: state is post-perm, contiguous --------------
    float sacc = 0.f;
    #pragma unroll
    for (int q = 0; q < 8; q++) {
        ulonglong2 v = st128[9 * tid + q];
        float2 v0 = *reinterpret_cast<float2*>(&v.x);
        float2 v1 = *reinterpret_cast<float2*>(&v.y);
        sacc += v0.x * v0.x + v0.y * v0.y + v1.x * v1.x + v1.y * v1.y;
    }
    // j = tid*16 + k: bit11 = tid7, bit10 = tid6, bit9 = tid5, bit8 = tid4
    float e01 = (((tid >> 7) ^ (tid >> 6)) & 1) ? -sacc : sacc;
    float e23 = (((tid >> 5) ^ (tid >> 4)) & 1) ? -sacc : sacc;

    #pragma unroll
    for (int off = 16; off > 0; off >>= 1) {
        e01 += __shfl_down_sync(0xffffffffu, e01, off);
        e23 += __shfl_down_sync(0xffffffffu, e23, off);
    }
    if ((tid & 31) == 0) { red0[tid >> 5] = e01; red1[tid >> 5] = e23; }
    __syncthreads();
    if (tid == 0) {
        float s1 = 0.f, s2 = 0.f;
        #pragma unroll
        for (int w = 0; w < NT / 32; w++) { s1 += red0[w]; s2 += red1[w]; }
        out[b * 2 + 0] = ow[0] * s1;
        out[b * 2 + 1] = ow[1] * s2;
    }
}

extern "C" void kernel_launch(void* const* d_in, const int* in_sizes, int n_in,
                              void* d_out, int out_size) {
    const float* x  = (const float*)d_in[0];   // (BATCH, 12)
    const float* iw = (const float*)d_in[1];   // (5, 12)
    const float* th = (const float*)d_in[2];   // (5, 12, 2)
    const float* ow = (const float*)d_in[3];   // (2,)
    float* out = (float*)d_out;                // (BATCH, 2)
    int batch = in_sizes[0] / NQ;
    qnet_kernel<<<batch, NT>>>(x, iw, th, ow, out);
}

// round 6
// speedup vs baseline: 2.8096x; 1.0199x over previous
#include <cuda_runtime.h>

#define NQ   12
#define DIM  4096
#define NL   5
#define NT   256
// pad-2 layout: loc(j) = j + 2*(j>>4)  -> stride-18 rows, 16B-aligned rows
#define PAD_DIM (DIM + 2 * (DIM / 16))   // 4608 ull = 36 KB

typedef unsigned long long ull;

__device__ __forceinline__ ull f32x2_mul(ull a, ull b) {
    ull r;
    asm("mul.rn.f32x2 %0, %1, %2;" : "=l"(r) : "l"(a), "l"(b));
    return r;
}
__device__ __forceinline__ ull f32x2_fma(ull a, ull b, ull c) {
    ull r;
    asm("fma.rn.f32x2 %0, %1, %2, %3;" : "=l"(r) : "l"(a), "l"(b), "l"(c));
    return r;
}
__device__ __forceinline__ ull swap_halves(ull v) {
    uint2 t = *reinterpret_cast<uint2*>(&v);
    uint2 s = make_uint2(t.y, t.x);
    return *reinterpret_cast<ull*>(&s);
}
__device__ __forceinline__ ull pack2(float lo, float hi) {
    uint2 t = make_uint2(__float_as_uint(lo), __float_as_uint(hi));
    return *reinterpret_cast<ull*>(&t);
}
__device__ __forceinline__ float2 cmul(float2 a, float2 b) {
    return make_float2(a.x * b.x - a.y * b.y, a.x * b.y + a.y * b.x);
}

// apply 4 gates: register-nibble bit m (pair stride 1<<m) <-> qubit QBASE - m
// U layout per qubit q: 4 x ulonglong2 = {c00,d00},{c01,d01},{c10,d10},{c11,d11}
template <int QBASE>
__device__ __forceinline__ void gates4p(ull a[16], const ulonglong2* __restrict__ U) {
    #pragma unroll
    for (int m = 0; m < 4; m++) {
        const int q = QBASE - m;
        const ulonglong2 p0 = U[q * 4 + 0];
        const ulonglong2 p1 = U[q * 4 + 1];
        const ulonglong2 p2 = U[q * 4 + 2];
        const ulonglong2 p3 = U[q * 4 + 3];
        #pragma unroll
        for (int k = 0; k < 16; k++) {
            if (!(k & (1 << m))) {
                ull s0 = a[k], s1 = a[k | (1 << m)];
                ull s0w = swap_halves(s0), s1w = swap_halves(s1);
                ull n0 = f32x2_mul(p0.x, s0);
                n0 = f32x2_fma(p0.y, s0w, n0);
                n0 = f32x2_fma(p1.x, s1,  n0);
                n0 = f32x2_fma(p1.y, s1w, n0);
                ull n1 = f32x2_mul(p2.x, s0);
                n1 = f32x2_fma(p2.y, s0w, n1);
                n1 = f32x2_fma(p3.x, s1,  n1);
                n1 = f32x2_fma(p3.y, s1w, n1);
                a[k] = n0; a[k | (1 << m)] = n1;
            }
        }
    }
}

__global__ void __launch_bounds__(NT, 4)
qnet_kernel(const float* __restrict__ x,
            const float* __restrict__ iw,
            const float* __restrict__ th,
            const float* __restrict__ ow,
            float* __restrict__ out) {
    __shared__ __align__(16) ull st[PAD_DIM];             // 36 KB packed state
    __shared__ __align__(16) ulonglong2 Up[NL * NQ * 4];  // all layers' gates
    __shared__ float2 U00s[NQ], U10s[NQ];                 // layer-0 col-0 entries
    __shared__ float red0[NT / 32], red1[NT / 32];

    const int b   = blockIdx.x;
    const int tid = threadIdx.x;

    // ---- build ALL layers' fused gates up front: one thread per (layer,qubit) ----
    if (tid < NL * NQ) {
        const int l = tid / NQ, q = tid % NQ;
        float xin = tanhf(x[b * NQ + q]);
        float g  = 0.5f * iw[l * NQ + q] * xin;
        float aa = 0.5f * th[(l * NQ + q) * 2 + 0];
        float bb = 0.5f * th[(l * NQ + q) * 2 + 1];
        float sg, cg, sa, ca, sb, cb;
        __sincosf(g,  &sg, &cg);
        __sincosf(aa, &sa, &ca);
        __sincosf(bb, &sb, &cb);
        float cc = ca * cg, ss = sa * sg, sc = sa * cg, cs = ca * sg;
        float2 e0 = make_float2(cb, -sb);
        float2 e1 = make_float2(cb,  sb);
        float2 u00 = cmul(e0, make_float2(cc,   ss));
        float2 u01 = cmul(e0, make_float2(-sc, -cs));
        float2 u10 = cmul(e1, make_float2(sc,  -cs));
        float2 u11 = cmul(e1, make_float2(cc,  -ss));
        ulonglong2* Uq = Up + (l * NQ + q) * 4;
        Uq[0] = make_ulonglong2(pack2(u00.x, u00.x), pack2(-u00.y, u00.y));
        Uq[1] = make_ulonglong2(pack2(u01.x, u01.x), pack2(-u01.y, u01.y));
        Uq[2] = make_ulonglong2(pack2(u10.x, u10.x), pack2(-u10.y, u10.y));
        Uq[3] = make_ulonglong2(pack2(u11.x, u11.x), pack2(-u11.y, u11.y));
        if (l == 0) { U00s[q] = u00; U10s[q] = u10; }
    }

    // ---- CNOT-ring scatter map (inverse perm), GF(2)-linear closed form ----
    // dst(j) = F(j); F(tid) = invgray(tid) ^ (parity(tid) << 11)
    int gt = tid ^ (tid >> 1); gt ^= gt >> 2; gt ^= gt >> 4;
    const int par_t = gt & 1;                 // parity(tid)
    const int F_t   = gt ^ (par_t << 11);
    // F(k<<8) for k = bits[11:8]
    const int DSTK[16] = {0x000, 0x9FF, 0xBFF, 0x200, 0xFFF, 0x600, 0x400, 0xDFF,
                          0x7FF, 0xE00, 0xC00, 0x5FF, 0x800, 0x1FF, 0x3FF, 0xA00};
    // measurement sign bits of DSTK[k]:  s01 = b11^b10,  s23 = b9^b8
    const bool S01K[16] = {0,1,1,0, 0,1,1,0, 1,0,0,1, 1,0,0,1};
    const bool S23K[16] = {0,1,0,1, 0,1,0,1, 0,1,0,1, 0,1,0,1};

    // phase base indices (ull units) in pad-2 layout
    const int bB = 18 * (tid & 0xF0) + (tid & 15);   // phase B: k at bB + 18k
    const int bC = tid + 2 * (tid >> 4);             // phase C: k at bC + 288k
    ulonglong2* st128 = reinterpret_cast<ulonglong2*>(st);

    ull a[16];
    __syncthreads();

    // ---------------- layer 0: product state, scatter-stored (post-perm) -------
    {
        float2 plow = make_float2(1.f, 0.f);
        #pragma unroll
        for (int p = 0; p < 8; p++) {                 // tid bit p <-> qubit 11-p
            float2 row = ((tid >> p) & 1) ? U10s[11 - p] : U00s[11 - p];
            plow = cmul(plow, row);
        }
        #pragma unroll
        for (int k = 0; k < 16; k++) {                // j = (k<<8) | tid
            float2 amp = plow;
            #pragma unroll
            for (int m = 0; m < 4; m++) {             // j bit 8+m <-> qubit 3-m
                float2 row = ((k >> m) & 1) ? U10s[3 - m] : U00s[3 - m];
                amp = cmul(amp, row);
            }
            int d = DSTK[k] ^ F_t;
            st[d + 2 * (d >> 4)] = pack2(amp.x, amp.y);
        }
    }
    __syncthreads();

    // ---------------- layers 1..4 ---------------------------------------------
    #pragma unroll 1
    for (int l = 1; l < NL; l++) {
        const ulonglong2* Ul = Up + l * (NQ * 4);

        // phase A: thread-local contiguous rows, 128-bit accesses
        #pragma unroll
        for (int q = 0; q < 8; q++) {
            ulonglong2 v = st128[9 * tid + q];
            a[2 * q] = v.x; a[2 * q + 1] = v.y;
        }
        gates4p<11>(a, Ul);                       // qubits 11,10,9,8 (bits 0..3)
        #pragma unroll
        for (int q = 0; q < 8; q++)
            st128[9 * tid + q] = make_ulonglong2(a[2 * q], a[2 * q + 1]);
        __syncwarp();                             // A->B exchange is intra-half-warp

        // phase B
        #pragma unroll
        for (int k = 0; k < 16; k++) a[k] = st[bB + 18 * k];
        gates4p<7>(a, Ul);                        // qubits 7,6,5,4 (bits 4..7)
        #pragma unroll
        for (int k = 0; k < 16; k++) st[bB + 18 * k] = a[k];
        __syncthreads();                          // B->C crosses warps

        // phase C
        #pragma unroll
        for (int k = 0; k < 16; k++) a[k] = st[bC + 288 * k];
        gates4p<3>(a, Ul);                        // qubits 3,2,1,0 (bits 8..11)
        if (l != NL - 1) {
            // CNOT-ring scatter for next layer
            #pragma unroll
            for (int k = 0; k < 16; k++) {
                int d = DSTK[k] ^ F_t;
                st[d + 2 * (d >> 4)] = a[k];
            }
            __syncthreads();
        }
    }

    // ---------------- measurement fused into last phase-C registers ------------
    // pre-perm j = (k<<8)|tid; post-perm s = F_t ^ DSTK[k];
    // sign01(s) = parity(tid) ^ S01K[k];  sign23(s) = S23K[k]  (F_t has no bits 8..10)
    float P0 = 0.f, P1 = 0.f, Q0 = 0.f, Q1 = 0.f;
    #pragma unroll
    for (int k = 0; k < 16; k++) {
        float2 v = *reinterpret_cast<float2*>(&a[k]);
        float pr = v.x * v.x + v.y * v.y;
        if (S01K[k]) P1 += pr; else P0 += pr;
        if (S23K[k]) Q1 += pr; else Q0 += pr;
    }
    float e01 = P0 - P1;
    if (par_t) e01 = -e01;
    float e23 = Q0 - Q1;

    #pragma unroll
    for (int off = 16; off > 0; off >>= 1) {
        e01 += __shfl_down_sync(0xffffffffu, e01, off);
        e23 += __shfl_down_sync(0xffffffffu, e23, off);
    }
    if ((tid & 31) == 0) { red0[tid >> 5] = e01; red1[tid >> 5] = e23; }
    __syncthreads();
    if (tid == 0) {
        float s1 = 0.f, s2 = 0.f;
        #pragma unroll
        for (int w = 0; w < NT / 32; w++) { s1 += red0[w]; s2 += red1[w]; }
        out[b * 2 + 0] = ow[0] * s1;
        out[b * 2 + 1] = ow[1] * s2;
    }
}

extern "C" void kernel_launch(void* const* d_in, const int* in_sizes, int n_in,
                              void* d_out, int out_size) {
    const float* x  = (const float*)d_in[0];   // (BATCH, 12)
    const float* iw = (const float*)d_in[1];   // (5, 12)
    const float* th = (const float*)d_in[2];   // (5, 12, 2)
    const float* ow = (const float*)d_in[3];   // (2,)
    float* out = (float*)d_out;                // (BATCH, 2)
    int batch = in_sizes[0] / NQ;
    qnet_kernel<<<batch, NT>>>(x, iw, th, ow, out);
}